// round 15
// baseline (speedup 1.0000x reference)
#include <cuda_runtime.h>
#include <cuda_fp16.h>
#include <cstdint>

#define BB   16
#define QN   4096
#define KVN  4096
#define DD   64
#define TQ   128
#define TK   128
#define SCALE_L2E 0.18033688011112042f   // 0.125 * log2(e)

// fp16 smem strides (elements); stride*2 mod 128B == 16 -> ldmatrix conflict-free
#define QSTR 72     // Q/K tiles: 128 x 64 (+8 pad)
#define PSTR 136    // P tile:   128 x 128 (+8 pad)
#define VSTR 136    // VT tile:   64 x 128 (+8 pad)

// smem byte offsets
#define OFF_QH   0
#define OFF_KH   (OFF_QH  + 128 * QSTR * 2)    // 18432
#define OFF_VTH  (OFF_KH  + 128 * QSTR * 2)    // 36864
#define OFF_PHI  (OFF_VTH + 64 * VSTR * 2)     // 54272
#define OFF_RSP  (OFF_PHI + 128 * PSTR * 2)    // 89088 (4 x 128 floats)
#define OFF_RS   (OFF_RSP + 4 * 128 * 4)       // 91136 (128 floats)
#define OFF_KSTG (OFF_RS + 128 * 4)            // 91648 (128 x 64 fp32)
#define OFF_VSTG (OFF_KSTG + 128 * 64 * 4)     // 124416 (128 x 68 fp32, padded)
#define SM_BYTES (OFF_VSTG + 128 * 68 * 4)     // 159232

__device__ float g_rowinv[BB * QN];
// fp16 staging for unnormalized P (disjoint from d_out -> no aliasing in K2)
__device__ __half2 g_pstage[(long)BB * QN * KVN / 2];

__device__ __forceinline__ uint32_t smem_u32(const void* p) {
    uint32_t a;
    asm("{ .reg .u64 t; cvta.to.shared.u64 t, %1; cvt.u32.u64 %0, t; }" : "=r"(a) : "l"(p));
    return a;
}

__device__ __forceinline__ float ex2(float x) {
    float r;
    asm("ex2.approx.ftz.f32 %0, %1;" : "=f"(r) : "f"(x));
    return r;
}

__device__ __forceinline__ void mma_f16(float* c, const uint32_t* a, const uint32_t* b) {
    asm("mma.sync.aligned.m16n8k16.row.col.f32.f16.f16.f32 "
        "{%0,%1,%2,%3}, {%4,%5,%6,%7}, {%8,%9}, {%0,%1,%2,%3};"
        : "+f"(c[0]), "+f"(c[1]), "+f"(c[2]), "+f"(c[3])
        : "r"(a[0]), "r"(a[1]), "r"(a[2]), "r"(a[3]), "r"(b[0]), "r"(b[1]));
}

__device__ __forceinline__ void ldm_x4(uint32_t* r, uint32_t addr) {
    asm volatile("ldmatrix.sync.aligned.m8n8.x4.shared.b16 {%0,%1,%2,%3}, [%4];"
        : "=r"(r[0]), "=r"(r[1]), "=r"(r[2]), "=r"(r[3]) : "r"(addr));
}

__device__ __forceinline__ void cp16(uint32_t sdst, const void* gsrc) {
    asm volatile("cp.async.cg.shared.global [%0], [%1], 16;" :: "r"(sdst), "l"(gsrc) : "memory");
}
#define CP_COMMIT() asm volatile("cp.async.commit_group;" ::: "memory")
#define CP_WAIT0()  asm volatile("cp.async.wait_group 0;" ::: "memory")

__global__ __launch_bounds__(256, 1)
void attn_k1(const float* __restrict__ q, const float* __restrict__ k,
             const float* __restrict__ v, float* __restrict__ out,
             int want_attn)
{
    extern __shared__ char smem[];
    const uint32_t sb = smem_u32(smem);
    const int tid  = threadIdx.x;
    const int lane = tid & 31;
    const int wid  = tid >> 5;
    const int g    = lane >> 2;
    const int tg   = lane & 3;
    const int wm   = wid >> 2;      // warp m (0..1) -> 64 rows
    const int wn   = wid & 3;       // warp n (0..3)
    const int b  = blockIdx.y;
    const int qt = (gridDim.x - 1) - blockIdx.x;   // longest blocks first
    const int q0 = qt * TQ;

    // ldmatrix per-lane address components
    const int aro = (lane & 7) + (lane & 8);
    const int aco = (lane >> 4) << 3;
    const int bro = ((lane >> 4) << 3) + (lane & 7);
    const int bco = (lane & 8);

    // per-thread staging coordinates
    const int kr_base = tid >> 4;            // + it*16
    const int kc = (tid & 15) * 4;
    const int vs0 = (tid & 63) * 2;          // V rows s0, s0+1
    const int vdb = (tid >> 6) * 16;         // 16 d's

    // P-export coordinates: thread -> (row, 64-col half)
    const int prow_cp = tid >> 1;
    const int pch_cp  = (tid & 1) * 64;

    // ---- prefetch tiles j=0 (K and V) ----
    {
        const float* kp = k + ((long)b * KVN) * DD;
        const float* vp = v + ((long)b * KVN) * DD;
        #pragma unroll
        for (int it = 0; it < 8; it++) {
            const int r = it * 16 + kr_base;
            cp16(sb + OFF_KSTG + (uint32_t)(r * 64 + kc) * 4, kp + r * DD + kc);
        }
        #pragma unroll
        for (int rr = 0; rr < 2; rr++)
            #pragma unroll
            for (int u = 0; u < 16; u += 4)
                cp16(sb + OFF_VSTG + (uint32_t)((vs0 + rr) * 68 + vdb + u) * 4,
                     vp + (vs0 + rr) * DD + vdb + u);
        CP_COMMIT();
    }

    // ---- load Q (pre-scaled by log2(e)/T) as single fp16 ----
    {
        const float* qp = q + ((long)b * QN + q0) * DD;
        #pragma unroll
        for (int it = 0; it < 8; it++) {
            const int r = it * 16 + kr_base;
            float4 t = *(const float4*)(qp + r * DD + kc);
            __half2 a = __floats2half2_rn(t.x * SCALE_L2E, t.y * SCALE_L2E);
            __half2 c2 = __floats2half2_rn(t.z * SCALE_L2E, t.w * SCALE_L2E);
            const uint32_t o = (uint32_t)(r * QSTR + kc) * 2;
            *(uint32_t*)(smem + OFF_QH + o)     = reinterpret_cast<uint32_t&>(a);
            *(uint32_t*)(smem + OFF_QH + o + 4) = reinterpret_cast<uint32_t&>(c2);
        }
    }

    float oacc[4][2][4];
    #pragma unroll
    for (int mt = 0; mt < 4; mt++)
        #pragma unroll
        for (int nt = 0; nt < 2; nt++)
            #pragma unroll
            for (int e = 0; e < 4; e++) oacc[mt][nt][e] = 0.f;
    float rs_acc = 0.f;

    CP_WAIT0();   // staging for j=0 ready (own-thread data)

    for (int j = 0; j <= qt; j++) {
        const int k0 = j * TK;

        // ---- convert staged K (fp32 -> single fp16 tile) ----
        #pragma unroll
        for (int it = 0; it < 8; it++) {
            const int r = it * 16 + kr_base;
            float4 t = *(const float4*)(smem + OFF_KSTG + (uint32_t)(r * 64 + kc) * 4);
            __half2 a = __floats2half2_rn(t.x, t.y);
            __half2 c2 = __floats2half2_rn(t.z, t.w);
            const uint32_t o = (uint32_t)(r * QSTR + kc) * 2;
            *(uint32_t*)(smem + OFF_KH + o)     = reinterpret_cast<uint32_t&>(a);
            *(uint32_t*)(smem + OFF_KH + o + 4) = reinterpret_cast<uint32_t&>(c2);
        }
        // ---- convert staged V -> transposed single fp16 VT tile ----
        #pragma unroll
        for (int u = 0; u < 16; u += 4) {
            float4 x = *(const float4*)(smem + OFF_VSTG + (uint32_t)(vs0 * 68 + vdb + u) * 4);
            float4 y = *(const float4*)(smem + OFF_VSTG + (uint32_t)((vs0 + 1) * 68 + vdb + u) * 4);
            const float xs[4] = {x.x, x.y, x.z, x.w};
            const float ys[4] = {y.x, y.y, y.z, y.w};
            #pragma unroll
            for (int e = 0; e < 4; e++) {
                __half2 hv = __floats2half2_rn(xs[e], ys[e]);
                *(uint32_t*)(smem + OFF_VTH + (uint32_t)((vdb + u + e) * VSTR + vs0) * 2) =
                    reinterpret_cast<uint32_t&>(hv);
            }
        }
        __syncthreads();

        // ---- prefetch tiles j+1 while computing ----
        if (j < qt) {
            const int k1n = k0 + TK;
            const float* kp = k + ((long)b * KVN + k1n) * DD;
            const float* vp = v + ((long)b * KVN + k1n) * DD;
            #pragma unroll
            for (int it = 0; it < 8; it++) {
                const int r = it * 16 + kr_base;
                cp16(sb + OFF_KSTG + (uint32_t)(r * 64 + kc) * 4, kp + r * DD + kc);
            }
            #pragma unroll
            for (int rr = 0; rr < 2; rr++)
                #pragma unroll
                for (int u = 0; u < 16; u += 4)
                    cp16(sb + OFF_VSTG + (uint32_t)((vs0 + rr) * 68 + vdb + u) * 4,
                         vp + (vs0 + rr) * DD + vdb + u);
        }
        CP_COMMIT();

        // ---- S = Q K^T : fp16 single pass, warp tile 64x32 (log2 domain) ----
        float sacc[4][4][4];
        #pragma unroll
        for (int mt = 0; mt < 4; mt++)
            #pragma unroll
            for (int nt = 0; nt < 4; nt++)
                #pragma unroll
                for (int e = 0; e < 4; e++) sacc[mt][nt][e] = 0.f;

        #pragma unroll
        for (int ks = 0; ks < 4; ks++) {
            uint32_t af[4][4];
            #pragma unroll
            for (int mt = 0; mt < 4; mt++)
                ldm_x4(af[mt], sb + OFF_QH +
                    (uint32_t)((wm * 64 + mt * 16 + aro) * QSTR + ks * 16 + aco) * 2);
            uint32_t bfr[4][2];
            #pragma unroll
            for (int np = 0; np < 2; np++) {
                uint32_t bw[4];
                ldm_x4(bw, sb + OFF_KH +
                    (uint32_t)((wn * 32 + np * 16 + bro) * QSTR + ks * 16 + bco) * 2);
                bfr[np * 2][0] = bw[0]; bfr[np * 2][1] = bw[1];
                bfr[np * 2 + 1][0] = bw[2]; bfr[np * 2 + 1][1] = bw[3];
            }
            #pragma unroll
            for (int mt = 0; mt < 4; mt++)
                #pragma unroll
                for (int nt = 0; nt < 4; nt++)
                    mma_f16(sacc[mt][nt], af[mt], bfr[nt]);
        }

        // ---- exp2 + mask + fp16 P into smem only ----
        const bool diag = (j == qt);
        float ps[8];
        #pragma unroll
        for (int i = 0; i < 8; i++) ps[i] = 0.f;
        #pragma unroll
        for (int mt = 0; mt < 4; mt++) {
            #pragma unroll
            for (int h = 0; h < 2; h++) {
                const int row  = wm * 64 + mt * 16 + g + h * 8;
                const int qrow = q0 + row;
                #pragma unroll
                for (int nt = 0; nt < 4; nt++) {
                    const int col = wn * 32 + nt * 8 + tg * 2;
                    float p0 = ex2(sacc[mt][nt][h * 2 + 0]);
                    float p1 = ex2(sacc[mt][nt][h * 2 + 1]);
                    if (diag) {
                        if (k0 + col > qrow)     p0 = 0.f;
                        if (k0 + col + 1 > qrow) p1 = 0.f;
                    }
                    ps[mt * 2 + h] += p0 + p1;
                    __half2 ph = __floats2half2_rn(p0, p1);
                    *(uint32_t*)(smem + OFF_PHI + (uint32_t)(row * PSTR + col) * 2) =
                        reinterpret_cast<uint32_t&>(ph);
                }
            }
        }
        #pragma unroll
        for (int i = 0; i < 8; i++) {
            ps[i] += __shfl_xor_sync(0xffffffffu, ps[i], 1);
            ps[i] += __shfl_xor_sync(0xffffffffu, ps[i], 2);
        }
        if (tg == 0) {
            #pragma unroll
            for (int mt = 0; mt < 4; mt++)
                #pragma unroll
                for (int h = 0; h < 2; h++) {
                    const int row = wm * 64 + mt * 16 + g + h * 8;
                    *(float*)(smem + OFF_RSP + (uint32_t)(wn * 128 + row) * 4) = ps[mt * 2 + h];
                }
        }
        __syncthreads();

        if (tid < 128) {
            rs_acc += *(float*)(smem + OFF_RSP + (uint32_t)(0 * 128 + tid) * 4)
                    + *(float*)(smem + OFF_RSP + (uint32_t)(1 * 128 + tid) * 4)
                    + *(float*)(smem + OFF_RSP + (uint32_t)(2 * 128 + tid) * 4)
                    + *(float*)(smem + OFF_RSP + (uint32_t)(3 * 128 + tid) * 4);
        }

        // ---- coalesced P export: smem tile -> g_pstage (128-bit stores) ----
        if (want_attn) {
            const __half* src = (const __half*)(smem + OFF_PHI) + prow_cp * PSTR + pch_cp;
            uint4* dst = (uint4*)(g_pstage +
                (((long)b * QN + q0 + prow_cp) * KVN + k0 + pch_cp) / 2);
            #pragma unroll
            for (int u = 0; u < 8; u++)
                dst[u] = *(const uint4*)(src + u * 8);
        }

        // ---- O += P V : fp16 single pass, warp tile 64x16 ----
        #pragma unroll
        for (int ks = 0; ks < 8; ks++) {
            uint32_t af[4][4];
            #pragma unroll
            for (int mt = 0; mt < 4; mt++)
                ldm_x4(af[mt], sb + OFF_PHI +
                    (uint32_t)((wm * 64 + mt * 16 + aro) * PSTR + ks * 16 + aco) * 2);
            uint32_t bw[4];
            ldm_x4(bw, sb + OFF_VTH +
                (uint32_t)((wn * 16 + bro) * VSTR + ks * 16 + bco) * 2);
            uint32_t bfr[2][2] = { { bw[0], bw[1] }, { bw[2], bw[3] } };
            #pragma unroll
            for (int mt = 0; mt < 4; mt++)
                #pragma unroll
                for (int nt = 0; nt < 2; nt++)
                    mma_f16(oacc[mt][nt], af[mt], bfr[nt]);
        }
        CP_WAIT0();          // next-iter staging arrived (own-thread data)
        __syncthreads();     // all readers of this iter's tiles done
    }

    // ---- epilogue: 1/l, O write ----
    if (tid < 128) {
        const float inv = 1.0f / rs_acc;
        *(float*)(smem + OFF_RS + (uint32_t)tid * 4) = inv;
        g_rowinv[b * QN + q0 + tid] = inv;
    }
    __syncthreads();

    if (out) {
        #pragma unroll
        for (int mt = 0; mt < 4; mt++) {
            #pragma unroll
            for (int h = 0; h < 2; h++) {
                const int row = wm * 64 + mt * 16 + g + h * 8;
                const float inv = *(const float*)(smem + OFF_RS + (uint32_t)row * 4);
                float* orow = out + ((long)b * QN + q0 + row) * DD;
                #pragma unroll
                for (int nt = 0; nt < 2; nt++) {
                    const int col = wn * 16 + nt * 8 + tg * 2;
                    *(float2*)(orow + col) = make_float2(oacc[mt][nt][h * 2 + 0] * inv,
                                                         oacc[mt][nt][h * 2 + 1] * inv);
                }
            }
        }
    }
}

// K2: flat streaming pass. One float4 of attn per thread: normalize from
// fp16 scratch (lower region) or zero-fill (strictly-upper region).
__global__ __launch_bounds__(256)
void attn_k2(float4* __restrict__ attn4)
{
    const long i = (long)blockIdx.x * 256 + threadIdx.x;  // float4 index
    const int  col4 = (int)(i & 1023);          // KVN/4 = 1024
    const long rest = i >> 10;
    const int  qrow = (int)(rest & 4095);
    const int  b    = (int)(rest >> 12);
    const int  qt = qrow >> 7;            // 128-row q tiles
    const int  kt = col4 >> 5;            // (col4*4)/128
    float4 r;
    if (kt > qt) {
        r = make_float4(0.f, 0.f, 0.f, 0.f);
    } else {
        const int rowid = (b << 12) | qrow;
        const uint2 pw = *(const uint2*)(g_pstage + ((long)rowid * KVN + col4 * 4) / 2);
        const float inv = g_rowinv[rowid];
        float2 f0 = __half22float2(reinterpret_cast<const __half2&>(pw.x));
        float2 f1 = __half22float2(reinterpret_cast<const __half2&>(pw.y));
        r = make_float4(f0.x * inv, f0.y * inv, f1.x * inv, f1.y * inv);
    }
    attn4[i] = r;
}

extern "C" void kernel_launch(void* const* d_in, const int* in_sizes, int n_in,
                              void* d_out, int out_size)
{
    const float* q = (const float*)d_in[0];
    const float* k = (const float*)d_in[1];
    const float* v = (const float*)d_in[2];

    const long OUTN = (long)BB * QN * DD;
    const long ATTN = (long)BB * QN * KVN;
    float* out  = nullptr;
    float* attn = nullptr;
    if ((long)out_size >= OUTN + ATTN) { out = (float*)d_out; attn = (float*)d_out + OUTN; }
    else if ((long)out_size == OUTN)   { out = (float*)d_out; }
    else                               { attn = (float*)d_out; }

    cudaFuncSetAttribute(attn_k1, cudaFuncAttributeMaxDynamicSharedMemorySize, SM_BYTES);

    dim3 g1(QN / TQ, BB);   // 32 x 16 blocks
    attn_k1<<<g1, 256, SM_BYTES>>>(q, k, v, out, attn ? 1 : 0);

    if (attn) {
        const unsigned nblk = (unsigned)((ATTN / 4) / 256);  // 262144
        attn_k2<<<nblk, 256>>>((float4*)attn);
    }
}

// round 17
// speedup vs baseline: 1.0369x; 1.0369x over previous
#include <cuda_runtime.h>
#include <cuda_fp16.h>
#include <cstdint>

#define BB   16
#define QN   4096
#define KVN  4096
#define DD   64
#define TQ   128
#define TK   128
#define SCALE_L2E 0.18033688011112042f   // 0.125 * log2(e)

// fp16 smem strides (elements); stride*2 mod 128B == 16 -> ldmatrix conflict-free
#define QSTR 72     // Q/K tiles: 128 x 64 (+8 pad)
#define PSTR 136    // P tile:   128 x 128 (+8 pad)
#define VSTR 136    // VT tile:   64 x 128 (+8 pad)

// smem byte offsets (double-buffered K / VT)
#define OFF_QH   0
#define OFF_KH0  (OFF_QH  + 128 * QSTR * 2)    // 18432
#define OFF_KH1  (OFF_KH0 + 128 * QSTR * 2)    // 36864
#define OFF_VT0  (OFF_KH1 + 128 * QSTR * 2)    // 55296
#define OFF_VT1  (OFF_VT0 + 64 * VSTR * 2)     // 72704
#define OFF_PHI  (OFF_VT1 + 64 * VSTR * 2)     // 90112
#define OFF_RSP  (OFF_PHI + 128 * PSTR * 2)    // 124928 (4 x 128 floats)
#define OFF_RS   (OFF_RSP + 4 * 128 * 4)       // 126976 (128 floats)
#define SM_BYTES (OFF_RS + 128 * 4)            // 127488

__device__ float g_rowinv[BB * QN];
__device__ __half2 g_pstage[(long)BB * QN * KVN / 2];  // unnormalized P
__device__ __half g_qh[(long)BB * QN * DD];            // Q * log2e/T, fp16
__device__ __half g_kh[(long)BB * KVN * DD];           // K fp16
__device__ __half g_vt[(long)BB * KVN * DD];           // V^T fp16: [b][kt][d][128]

__device__ __forceinline__ uint32_t smem_u32(const void* p) {
    uint32_t a;
    asm("{ .reg .u64 t; cvta.to.shared.u64 t, %1; cvt.u32.u64 %0, t; }" : "=r"(a) : "l"(p));
    return a;
}
__device__ __forceinline__ float ex2(float x) {
    float r;
    asm("ex2.approx.ftz.f32 %0, %1;" : "=f"(r) : "f"(x));
    return r;
}
__device__ __forceinline__ void mma_f16(float* c, const uint32_t* a, const uint32_t* b) {
    asm("mma.sync.aligned.m16n8k16.row.col.f32.f16.f16.f32 "
        "{%0,%1,%2,%3}, {%4,%5,%6,%7}, {%8,%9}, {%0,%1,%2,%3};"
        : "+f"(c[0]), "+f"(c[1]), "+f"(c[2]), "+f"(c[3])
        : "r"(a[0]), "r"(a[1]), "r"(a[2]), "r"(a[3]), "r"(b[0]), "r"(b[1]));
}
__device__ __forceinline__ void ldm_x4(uint32_t* r, uint32_t addr) {
    asm volatile("ldmatrix.sync.aligned.m8n8.x4.shared.b16 {%0,%1,%2,%3}, [%4];"
        : "=r"(r[0]), "=r"(r[1]), "=r"(r[2]), "=r"(r[3]) : "r"(addr));
}
__device__ __forceinline__ void cp16(uint32_t sdst, const void* gsrc) {
    asm volatile("cp.async.cg.shared.global [%0], [%1], 16;" :: "r"(sdst), "l"(gsrc) : "memory");
}
#define CP_COMMIT() asm volatile("cp.async.commit_group;" ::: "memory")
#define CP_WAIT1()  asm volatile("cp.async.wait_group 1;" ::: "memory")

// ---- K0a: convert Q (scaled) and K to fp16 ----
#define NQ4 (BB * QN * DD / 4)   // 1,048,576 float4-groups per tensor
__global__ __launch_bounds__(256)
void conv_qk(const float* __restrict__ q, const float* __restrict__ k)
{
    const long i = (long)blockIdx.x * 256 + threadIdx.x;
    if (i < NQ4) {
        float4 t = *(const float4*)(q + i * 4);
        __half2 a = __floats2half2_rn(t.x * SCALE_L2E, t.y * SCALE_L2E);
        __half2 b = __floats2half2_rn(t.z * SCALE_L2E, t.w * SCALE_L2E);
        uint2 w = { reinterpret_cast<uint32_t&>(a), reinterpret_cast<uint32_t&>(b) };
        *(uint2*)(g_qh + i * 4) = w;
    } else {
        const long j = i - NQ4;
        float4 t = *(const float4*)(k + j * 4);
        __half2 a = __floats2half2_rn(t.x, t.y);
        __half2 b = __floats2half2_rn(t.z, t.w);
        uint2 w = { reinterpret_cast<uint32_t&>(a), reinterpret_cast<uint32_t&>(b) };
        *(uint2*)(g_kh + j * 4) = w;
    }
}

// ---- K0b: transpose V tiles to fp16 g_vt[b][kt][d][128] ----
__global__ __launch_bounds__(256)
void vtrans(const float* __restrict__ v)
{
    __shared__ __half tl[128][72];
    const int bid = blockIdx.x;            // b*32 + kt
    const int t = threadIdx.x;
    const long vbase = (long)(bid >> 5) * KVN * DD + (long)(bid & 31) * TK * DD;

    const int s = t >> 1, dh = (t & 1) * 32;
    const float* src = v + vbase + (long)s * DD + dh;
    #pragma unroll
    for (int i = 0; i < 8; i++) {
        float4 x = *(const float4*)(src + i * 4);
        __half2 a = __floats2half2_rn(x.x, x.y);
        __half2 b = __floats2half2_rn(x.z, x.w);
        *(uint32_t*)&tl[s][dh + i * 4]     = reinterpret_cast<uint32_t&>(a);
        *(uint32_t*)&tl[s][dh + i * 4 + 2] = reinterpret_cast<uint32_t&>(b);
    }
    __syncthreads();

    const int d = t >> 2, sq = (t & 3) * 32;
    __half* dst = g_vt + ((long)bid * DD + d) * 128 + sq;
    #pragma unroll
    for (int i = 0; i < 16; i++) {
        __half2 p = { tl[sq + 2 * i][d], tl[sq + 2 * i + 1][d] };
        *(uint32_t*)(dst + 2 * i) = reinterpret_cast<uint32_t&>(p);
    }
}

__global__ __launch_bounds__(256, 1)
void attn_k1(float* __restrict__ out, int want_attn)
{
    extern __shared__ char smem[];
    const uint32_t sb = smem_u32(smem);
    const int tid  = threadIdx.x;
    const int lane = tid & 31;
    const int wid  = tid >> 5;
    const int g    = lane >> 2;
    const int tg   = lane & 3;
    const int wm   = wid >> 2;      // warp m (0..1) -> 64 rows
    const int wn   = wid & 3;       // warp n (0..3)
    const int b  = blockIdx.y;
    const int qt = (gridDim.x - 1) - blockIdx.x;   // longest blocks first
    const int q0 = qt * TQ;

    // ldmatrix per-lane address components
    const int aro = (lane & 7) + (lane & 8);
    const int aco = (lane >> 4) << 3;
    const int bro = ((lane >> 4) << 3) + (lane & 7);
    const int bco = (lane & 8);

    // cp.async coordinates
    const int qr = tid >> 1, qh2 = (tid & 1);       // Q/K: row, 32-half half
    const int vd = tid >> 2, vq = (tid & 3);        // VT: d row, 32-half quarter

    // ---- pre-loop: Q tile + j=0 K/VT into buf0 ----
    {
        const __half* qsrc = g_qh + ((long)b * QN + q0 + qr) * DD + qh2 * 32;
        #pragma unroll
        for (int i = 0; i < 4; i++)
            cp16(sb + OFF_QH + (uint32_t)(qr * QSTR + qh2 * 32 + i * 8) * 2, qsrc + i * 8);
        const __half* ksrc = g_kh + ((long)b * KVN + qr) * DD + qh2 * 32;
        #pragma unroll
        for (int i = 0; i < 4; i++)
            cp16(sb + OFF_KH0 + (uint32_t)(qr * QSTR + qh2 * 32 + i * 8) * 2, ksrc + i * 8);
        const __half* vsrc = g_vt + ((long)b * 32 * DD + vd) * 128 + vq * 32;
        #pragma unroll
        for (int i = 0; i < 4; i++)
            cp16(sb + OFF_VT0 + (uint32_t)(vd * VSTR + vq * 32 + i * 8) * 2, vsrc + i * 8);
        CP_COMMIT();
    }

    float oacc[4][2][4];
    float pacc[8];
    #pragma unroll
    for (int mt = 0; mt < 4; mt++)
        #pragma unroll
        for (int nt = 0; nt < 2; nt++)
            #pragma unroll
            for (int e = 0; e < 4; e++) oacc[mt][nt][e] = 0.f;
    #pragma unroll
    for (int i = 0; i < 8; i++) pacc[i] = 0.f;

    for (int j = 0; j <= qt; j++) {
        const int k0 = j * TK;
        const uint32_t kh = (j & 1) ? OFF_KH1 : OFF_KH0;
        const uint32_t vt = (j & 1) ? OFF_VT1 : OFF_VT0;

        // ---- issue cp.async for j+1 into the other buffers ----
        if (j < qt) {
            const uint32_t kh_n = (j & 1) ? OFF_KH0 : OFF_KH1;
            const uint32_t vt_n = (j & 1) ? OFF_VT0 : OFF_VT1;
            const __half* ksrc = g_kh + ((long)b * KVN + k0 + TK + qr) * DD + qh2 * 32;
            #pragma unroll
            for (int i = 0; i < 4; i++)
                cp16(sb + kh_n + (uint32_t)(qr * QSTR + qh2 * 32 + i * 8) * 2, ksrc + i * 8);
            const __half* vsrc = g_vt + ((long)b * 32 * DD + (long)(j + 1) * DD + vd) * 128 + vq * 32;
            #pragma unroll
            for (int i = 0; i < 4; i++)
                cp16(sb + vt_n + (uint32_t)(vd * VSTR + vq * 32 + i * 8) * 2, vsrc + i * 8);
        }
        CP_COMMIT();
        CP_WAIT1();          // tiles for j (and Q) have landed
        __syncthreads();     // visible to all warps

        // ---- S = Q K^T : fp16 single pass, warp tile 64x32 (log2 domain) ----
        float sacc[4][4][4];
        #pragma unroll
        for (int mt = 0; mt < 4; mt++)
            #pragma unroll
            for (int nt = 0; nt < 4; nt++)
                #pragma unroll
                for (int e = 0; e < 4; e++) sacc[mt][nt][e] = 0.f;

        #pragma unroll
        for (int ks = 0; ks < 4; ks++) {
            uint32_t af[4][4];
            #pragma unroll
            for (int mt = 0; mt < 4; mt++)
                ldm_x4(af[mt], sb + OFF_QH +
                    (uint32_t)((wm * 64 + mt * 16 + aro) * QSTR + ks * 16 + aco) * 2);
            uint32_t bfr[4][2];
            #pragma unroll
            for (int np = 0; np < 2; np++) {
                uint32_t bw[4];
                ldm_x4(bw, sb + kh +
                    (uint32_t)((wn * 32 + np * 16 + bro) * QSTR + ks * 16 + bco) * 2);
                bfr[np * 2][0] = bw[0]; bfr[np * 2][1] = bw[1];
                bfr[np * 2 + 1][0] = bw[2]; bfr[np * 2 + 1][1] = bw[3];
            }
            #pragma unroll
            for (int mt = 0; mt < 4; mt++)
                #pragma unroll
                for (int nt = 0; nt < 4; nt++)
                    mma_f16(sacc[mt][nt], af[mt], bfr[nt]);
        }

        // ---- exp2 + mask + fp16 P to smem + g_pstage store ----
        const bool diag = (j == qt);
        #pragma unroll
        for (int mt = 0; mt < 4; mt++) {
            #pragma unroll
            for (int h = 0; h < 2; h++) {
                const int row  = wm * 64 + mt * 16 + g + h * 8;
                const int qrow = q0 + row;
                __half2* prow = want_attn ?
                    g_pstage + (((long)b * QN + qrow) * KVN + k0) / 2 : nullptr;
                #pragma unroll
                for (int nt = 0; nt < 4; nt++) {
                    const int col = wn * 32 + nt * 8 + tg * 2;
                    float p0 = ex2(sacc[mt][nt][h * 2 + 0]);
                    float p1 = ex2(sacc[mt][nt][h * 2 + 1]);
                    if (diag) {
                        if (k0 + col > qrow)     p0 = 0.f;
                        if (k0 + col + 1 > qrow) p1 = 0.f;
                    }
                    pacc[mt * 2 + h] += p0 + p1;
                    __half2 ph = __floats2half2_rn(p0, p1);
                    if (prow) prow[col >> 1] = ph;
                    *(uint32_t*)(smem + OFF_PHI + (uint32_t)(row * PSTR + col) * 2) =
                        reinterpret_cast<uint32_t&>(ph);
                }
            }
        }
        __syncthreads();     // P tile visible

        // ---- O += P V : fp16 single pass, warp tile 64x16 ----
        #pragma unroll
        for (int ks = 0; ks < 8; ks++) {
            uint32_t af[4][4];
            #pragma unroll
            for (int mt = 0; mt < 4; mt++)
                ldm_x4(af[mt], sb + OFF_PHI +
                    (uint32_t)((wm * 64 + mt * 16 + aro) * PSTR + ks * 16 + aco) * 2);
            uint32_t bw[4];
            ldm_x4(bw, sb + vt +
                (uint32_t)((wn * 16 + bro) * VSTR + ks * 16 + bco) * 2);
            uint32_t bfr[2][2] = { { bw[0], bw[1] }, { bw[2], bw[3] } };
            #pragma unroll
            for (int mt = 0; mt < 4; mt++)
                #pragma unroll
                for (int nt = 0; nt < 2; nt++)
                    mma_f16(oacc[mt][nt], af[mt], bfr[nt]);
        }
        __syncthreads();     // buf[j] reads done before j+1 overwrites its pair
    }

    // ---- reduce rowsum partials across the 4 tg lanes, then across wn warps ----
    #pragma unroll
    for (int i = 0; i < 8; i++) {
        pacc[i] += __shfl_xor_sync(0xffffffffu, pacc[i], 1);
        pacc[i] += __shfl_xor_sync(0xffffffffu, pacc[i], 2);
    }
    if (tg == 0) {
        #pragma unroll
        for (int mt = 0; mt < 4; mt++)
            #pragma unroll
            for (int h = 0; h < 2; h++) {
                const int row = wm * 64 + mt * 16 + g + h * 8;
                *(float*)(smem + OFF_RSP + (uint32_t)(wn * 128 + row) * 4) = pacc[mt * 2 + h];
            }
    }
    __syncthreads();
    if (tid < 128) {
        const float rs = *(float*)(smem + OFF_RSP + (uint32_t)(0 * 128 + tid) * 4)
                       + *(float*)(smem + OFF_RSP + (uint32_t)(1 * 128 + tid) * 4)
                       + *(float*)(smem + OFF_RSP + (uint32_t)(2 * 128 + tid) * 4)
                       + *(float*)(smem + OFF_RSP + (uint32_t)(3 * 128 + tid) * 4);
        const float inv = 1.0f / rs;
        *(float*)(smem + OFF_RS + (uint32_t)tid * 4) = inv;
        g_rowinv[b * QN + q0 + tid] = inv;
    }
    __syncthreads();

    if (out) {
        #pragma unroll
        for (int mt = 0; mt < 4; mt++) {
            #pragma unroll
            for (int h = 0; h < 2; h++) {
                const int row = wm * 64 + mt * 16 + g + h * 8;
                const float inv = *(const float*)(smem + OFF_RS + (uint32_t)row * 4);
                float* orow = out + ((long)b * QN + q0 + row) * DD;
                #pragma unroll
                for (int nt = 0; nt < 2; nt++) {
                    const int col = wn * 16 + nt * 8 + tg * 2;
                    *(float2*)(orow + col) = make_float2(oacc[mt][nt][h * 2 + 0] * inv,
                                                         oacc[mt][nt][h * 2 + 1] * inv);
                }
            }
        }
    }
}

// K2: streaming normalize/zero-fill; 32 B of attn per thread.
__global__ __launch_bounds__(256)
void attn_k2(float* __restrict__ attn)
{
    const long i = (long)blockIdx.x * 256 + threadIdx.x;  // 8-float chunk index
    const int  c8   = (int)(i & 511) * 8;       // col (KVN/8 = 512 chunks)
    const long rest = i >> 9;
    const int  qrow = (int)(rest & 4095);
    const int  b    = (int)(rest >> 12);
    const int  qt = qrow >> 7;
    const int  kt = c8 >> 7;
    float4* dst = (float4*)(attn + i * 8);
    float4 r0, r1;
    if (kt > qt) {
        r0 = make_float4(0.f, 0.f, 0.f, 0.f);
        r1 = r0;
    } else {
        const int rowid = (b << 12) | qrow;
        const uint4 pw = *(const uint4*)(g_pstage + ((long)rowid * KVN + c8) / 2);
        const float inv = g_rowinv[rowid];
        float2 f0 = __half22float2(reinterpret_cast<const __half2&>(pw.x));
        float2 f1 = __half22float2(reinterpret_cast<const __half2&>(pw.y));
        float2 f2 = __half22float2(reinterpret_cast<const __half2&>(pw.z));
        float2 f3 = __half22float2(reinterpret_cast<const __half2&>(pw.w));
        r0 = make_float4(f0.x * inv, f0.y * inv, f1.x * inv, f1.y * inv);
        r1 = make_float4(f2.x * inv, f2.y * inv, f3.x * inv, f3.y * inv);
    }
    dst[0] = r0;
    dst[1] = r1;
}

extern "C" void kernel_launch(void* const* d_in, const int* in_sizes, int n_in,
                              void* d_out, int out_size)
{
    const float* q = (const float*)d_in[0];
    const float* k = (const float*)d_in[1];
    const float* v = (const float*)d_in[2];

    const long OUTN = (long)BB * QN * DD;
    const long ATTN = (long)BB * QN * KVN;
    float* out  = nullptr;
    float* attn = nullptr;
    if ((long)out_size >= OUTN + ATTN) { out = (float*)d_out; attn = (float*)d_out + OUTN; }
    else if ((long)out_size == OUTN)   { out = (float*)d_out; }
    else                               { attn = (float*)d_out; }

    conv_qk<<<2 * NQ4 / 256, 256>>>(q, k);
    vtrans<<<BB * (KVN / TK), 256>>>(v);

    cudaFuncSetAttribute(attn_k1, cudaFuncAttributeMaxDynamicSharedMemorySize, SM_BYTES);
    dim3 g1(QN / TQ, BB);   // 32 x 16 blocks
    attn_k1<<<g1, 256, SM_BYTES>>>(out, attn ? 1 : 0);

    if (attn) {
        const unsigned nblk = (unsigned)((ATTN / 8) / 256);  // 131072
        attn_k2<<<nblk, 256>>>(attn);
    }
}